// round 15
// baseline (speedup 1.0000x reference)
#include <cuda_runtime.h>
#include <cuda_fp16.h>
#include <cstdint>

// Problem constants
#define B_  32
#define T_  1000
#define I_  3
#define R_  2048
#define O_  3

#define CAP   160        // per-row nnz capacity (padded to mult of 32)
#define GRID  128        // CTAs / row-blocks
#define RPC   16         // rows per block
#define NTHR  512
#define CAPU  512        // unknown-list capacity per (t, block) == max possible (16*32)

// ---------------- device scratch ----------------
__device__ __half            g_s16[(size_t)(T_ + 1) * R_ * B_];   // dense fp16 states
__device__ float             g_final[R_ * B_];                    // fp32 final state
__device__ unsigned          g_cols[R_][CAP];                     // col*32 (half-offset of row)
__device__ float             g_vals[R_][CAP];
__device__ int               g_cnt[R_];                           // padded to mult of 32
__device__ float             g_thresh[R_];                        // L1(row)+margin
__device__ int               g_ucnt[T_ * GRID];                   // unknown counts
__device__ uint2             g_unk[(size_t)T_ * GRID * CAPU];     // (rl<<5|b, ax bits)
__device__ volatile unsigned g_flag[GRID * 32];                   // 128B line per CTA

// ---------------- helpers ----------------
__device__ __forceinline__ unsigned ld_acq(const volatile unsigned* p) {
    unsigned v;
    asm volatile("ld.acquire.gpu.u32 %0, [%1];" : "=r"(v) : "l"((const unsigned*)p) : "memory");
    return v;
}
__device__ __forceinline__ void st_rel(volatile unsigned* p, unsigned v) {
    asm volatile("st.release.gpu.u32 [%0], %1;" :: "l"((unsigned*)p), "r"(v) : "memory");
}
__device__ __forceinline__ float tanh_fast(float x) {
    float y;
    asm("tanh.approx.f32 %0, %1;" : "=f"(y) : "f"(x));
    return y;
}

// ---------------- P1: compaction, L1 norms, per-launch resets ----------------
__global__ void prep_kernel(const float* __restrict__ W) {
    int r = blockIdx.x;
    int lane = threadIdx.x;
    const float* row = W + (size_t)r * R_;

    int base = 0;
    float l1 = 0.0f;
    for (int c0 = 0; c0 < R_; c0 += 32) {
        float v = row[c0 + lane];
        l1 += fabsf(v);
        unsigned m = __ballot_sync(0xffffffffu, v != 0.0f);
        if (v != 0.0f) {
            int p = base + __popc(m & ((1u << lane) - 1u));
            if (p < CAP) {
                g_cols[r][p] = (unsigned)(c0 + lane) * 32u;   // half units: row stride 32
                g_vals[r][p] = v;
            }
        }
        base += __popc(m);
    }
    #pragma unroll
    for (int d = 16; d; d >>= 1) l1 += __shfl_xor_sync(0xffffffffu, l1, d);

    if (base > CAP) base = CAP;
    int padded = (base + 31) & ~31;
    if (padded < 32) padded = 32;
    if (padded > CAP) padded = CAP;           // CAP multiple of 32
    for (int p = base + lane; p < padded; p += 32) {
        g_cols[r][p] = ((unsigned)(r * 7 + p * 13) & (R_ - 1)) * 32u;
        g_vals[r][p] = 0.0f;
    }
    if (lane == 0) {
        g_cnt[r] = padded;
        g_thresh[r] = l1 + 10.5f;             // saturation margin (fp32 tanh==1 beyond 9.01)
    }

    // per-launch resets (graph replay safe)
    g_s16[(size_t)r * B_ + lane] = __float2half(0.0f);   // state_0 = 0
    if (r < GRID && lane == 0) g_flag[r << 5] = 0u;
    int gidx = r * 32 + lane;                             // zero 128000 counters
    if (gidx < T_ * GRID) g_ucnt[gidx] = 0;
    gidx += 65536;
    if (gidx < T_ * GRID) g_ucnt[gidx] = 0;
}

// ---------------- P2a: parallel-over-t classification + saturated states ------
__global__ void __launch_bounds__(NTHR)
phaseA_kernel(const float* __restrict__ x,        // [B,T,I]
              const float* __restrict__ win,      // [R,I]
              const float* __restrict__ noise,    // [B,R]
              float* __restrict__ states_out) {   // [B,T,R]
    __shared__ float ftile[RPC][B_ + 1];

    const int t  = blockIdx.y;
    const int rb = blockIdx.x;
    const int tid = threadIdx.x;
    const int rl = tid >> 5;                  // local row (warp)
    const int b  = tid & 31;                  // batch (lane)
    const int r  = rb * RPC + rl;

    const float* xb = x + (size_t)b * (T_ * I_) + t * I_;
    float ax = fmaf(win[r * 3 + 0], xb[0],
               fmaf(win[r * 3 + 1], xb[1],
               fmaf(win[r * 3 + 2], xb[2], noise[(size_t)b * R_ + r])));

    float val = 0.0f;                          // placeholder for unknowns
    if (fabsf(ax) > g_thresh[r]) {
        val = (ax > 0.0f) ? 1.0f : -1.0f;      // exact: tanh saturates regardless of rec
    } else {
        int slot = atomicAdd(&g_ucnt[t * GRID + rb], 1);   // slot < 512 by construction
        g_unk[((size_t)(t * GRID + rb) << 9) + slot] =
            make_uint2((unsigned)((rl << 5) | b), __float_as_uint(ax));
    }

    // dense fp16 state for step t+1 (warp-coalesced 64B per row)
    g_s16[(size_t)(t + 1) * (R_ * B_) + (size_t)r * B_ + b] = __float2half_rn(val);
    if (t == T_ - 1) g_final[r * B_ + b] = val;            // phaseB overwrites unknowns

    // transposed states_out write via SMEM (64B per half-warp)
    ftile[rl][b] = val;
    __syncthreads();
    {
        int b2 = rl + ((b >> 4) << 4);         // warp rl writes batches rl and rl+16
        int rr = b & 15;
        states_out[(size_t)b2 * (T_ * R_) + (size_t)t * R_ + rb * RPC + rr] = ftile[rr][b2];
    }
}

// ---------------- P2b: serial resolution of unsaturated entries ----------------
__global__ void __launch_bounds__(NTHR, 1)
phaseB_kernel(float* __restrict__ states_out) {  // [B,T,R]
    __shared__ uint2 snnz[RPC][CAP];             // (col*32, val bits) 20 KB
    __shared__ int   scnt[RPC];

    const int tid  = threadIdx.x;
    const int wid  = tid >> 5;                   // warp id (0..15)
    const int lane = tid & 31;
    const int cta  = blockIdx.x;

    // preload this block's 16 rows of nnz (reused all steps)
    {
        int r = cta * RPC + wid;
        int cnt = g_cnt[r];
        if (lane == 0) scnt[wid] = cnt;
        for (int k = lane; k < cnt; k += 32)
            snnz[wid][k] = make_uint2(g_cols[r][k], __float_as_uint(g_vals[r][k]));
    }
    __syncthreads();

    for (int tau = 1; tau <= T_; tau++) {
        const __half* sp = g_s16 + (size_t)(tau - 1) * (R_ * B_);
        const int lbase = (tau - 1) * GRID + cta;
        const int ucnt = g_ucnt[lbase];

        for (int i = wid; i < ucnt; i += 16) {   // one warp per unknown pair
            uint2 e = g_unk[((size_t)lbase << 9) + i];
            int rl = (int)(e.x >> 5);
            int b  = (int)(e.x & 31);
            int pc = scnt[rl];

            float part = 0.0f;
            for (int k = lane; k < pc; k += 32) {
                uint2 cv = snnz[rl][k];
                part = fmaf(__uint_as_float(cv.y),
                            __half2float(sp[cv.x + b]), part);
            }
            #pragma unroll
            for (int d = 16; d; d >>= 1) part += __shfl_xor_sync(0xffffffffu, part, d);

            if (lane == 0) {
                float v = tanh_fast(__uint_as_float(e.y) + part);
                int rg = cta * RPC + rl;
                g_s16[(size_t)tau * (R_ * B_) + (size_t)rg * B_ + b] = __float2half_rn(v);
                states_out[(size_t)b * (T_ * R_) + (size_t)(tau - 1) * R_ + rg] = v;
                if (tau == T_) g_final[rg * B_ + b] = v;
            }
        }
        __syncthreads();                         // all corrections stored

        // arrival (release orders prior stores; bar.sync cumulative) + flat poll
        if (tid == 0) st_rel(&g_flag[cta << 5], (unsigned)tau);
        if (tid < GRID) {
            while (ld_acq(&g_flag[tid << 5]) < (unsigned)tau) { }
        }
        __syncthreads();
    }
}

// ---------------- P3: output projection ----------------
__global__ void outproj_kernel(const float* __restrict__ wout,  // [O,R]
                               float* __restrict__ out) {       // [B*O]
    __shared__ float red[256];
    int pair = blockIdx.x;            // 0..95
    int b = pair / O_, o = pair - b * O_;

    float sum = 0.0f;
    for (int r = threadIdx.x; r < R_; r += blockDim.x)
        sum += g_final[r * B_ + b] * wout[o * R_ + r];

    red[threadIdx.x] = sum;
    __syncthreads();
    for (int s = 128; s > 0; s >>= 1) {
        if (threadIdx.x < s) red[threadIdx.x] += red[threadIdx.x + s];
        __syncthreads();
    }
    if (threadIdx.x == 0) out[b * O_ + o] = red[0];
}

// ---------------- launch ----------------
extern "C" void kernel_launch(void* const* d_in, const int* in_sizes, int n_in,
                              void* d_out, int out_size) {
    (void)in_sizes; (void)n_in; (void)out_size;
    const float* x     = (const float*)d_in[0];   // [B,T,I]
    const float* win   = (const float*)d_in[1];   // [R,I]
    const float* wres  = (const float*)d_in[2];   // [R,R]
    const float* wout  = (const float*)d_in[3];   // [O,R]
    const float* noise = (const float*)d_in[4];   // [B,R]
    float* out = (float*)d_out;                   // [B*O] then [B,T,R]

    prep_kernel<<<R_, 32>>>(wres);
    phaseA_kernel<<<dim3(GRID, T_), NTHR>>>(x, win, noise, out + B_ * O_);
    phaseB_kernel<<<GRID, NTHR>>>(out + B_ * O_);
    outproj_kernel<<<B_ * O_, 256>>>(wout, out);
}

// round 16
// speedup vs baseline: 1.2292x; 1.2292x over previous
#include <cuda_runtime.h>
#include <cuda_fp16.h>
#include <cstdint>

// Problem constants
#define B_  32
#define T_  1000
#define I_  3
#define R_  2048
#define O_  3

#define CAP    160       // per-row nnz capacity (padded to mult of 32)
#define GRID   128       // CTAs / row-blocks
#define RPC    16        // rows per block
#define NTHR   512
#define CAPU   512       // unknown-list capacity per (t, block) == max possible (16*32)
#define TCHUNK 25        // timesteps per phaseA block (40 * 25 = 1000)

// ---------------- device scratch ----------------
__device__ __half            g_s16[(size_t)(T_ + 1) * R_ * B_];   // dense fp16 states
__device__ float             g_final[R_ * B_];                    // fp32 final state
__device__ unsigned          g_cols[R_][CAP];                     // col*32 (half-offset of row)
__device__ float             g_vals[R_][CAP];
__device__ int               g_cnt[R_];                           // padded to mult of 32
__device__ float             g_thresh[R_];                        // L1(row)+margin
__device__ int               g_ucnt[T_ * GRID];                   // unknown counts
__device__ uint2             g_unk[(size_t)T_ * GRID * CAPU];     // (rl<<5|b, ax bits)
__device__ volatile unsigned g_flag[GRID * 32];                   // 128B line per CTA

// ---------------- helpers ----------------
__device__ __forceinline__ unsigned ld_acq(const volatile unsigned* p) {
    unsigned v;
    asm volatile("ld.acquire.gpu.u32 %0, [%1];" : "=r"(v) : "l"((const unsigned*)p) : "memory");
    return v;
}
__device__ __forceinline__ void st_rel(volatile unsigned* p, unsigned v) {
    asm volatile("st.release.gpu.u32 [%0], %1;" :: "l"((unsigned*)p), "r"(v) : "memory");
}
__device__ __forceinline__ float tanh_fast(float x) {
    float y;
    asm("tanh.approx.f32 %0, %1;" : "=f"(y) : "f"(x));
    return y;
}
__device__ __forceinline__ void prefetch_l2(const void* p) {
    asm volatile("prefetch.global.L2 [%0];" :: "l"(p));
}

// ---------------- P1: compaction, L1 norms, per-launch resets ----------------
__global__ void prep_kernel(const float* __restrict__ W) {
    int r = blockIdx.x;
    int lane = threadIdx.x;
    const float* row = W + (size_t)r * R_;

    int base = 0;
    float l1 = 0.0f;
    for (int c0 = 0; c0 < R_; c0 += 32) {
        float v = row[c0 + lane];
        l1 += fabsf(v);
        unsigned m = __ballot_sync(0xffffffffu, v != 0.0f);
        if (v != 0.0f) {
            int p = base + __popc(m & ((1u << lane) - 1u));
            if (p < CAP) {
                g_cols[r][p] = (unsigned)(c0 + lane) * 32u;   // half units: row stride 32
                g_vals[r][p] = v;
            }
        }
        base += __popc(m);
    }
    #pragma unroll
    for (int d = 16; d; d >>= 1) l1 += __shfl_xor_sync(0xffffffffu, l1, d);

    if (base > CAP) base = CAP;
    int padded = (base + 31) & ~31;
    if (padded < 32) padded = 32;
    if (padded > CAP) padded = CAP;
    for (int p = base + lane; p < padded; p += 32) {
        g_cols[r][p] = ((unsigned)(r * 7 + p * 13) & (R_ - 1)) * 32u;
        g_vals[r][p] = 0.0f;
    }
    if (lane == 0) {
        g_cnt[r] = padded;
        g_thresh[r] = l1 + 10.5f;             // saturation margin (fp32 tanh==1 beyond ~9.01)
    }

    // per-launch resets (graph replay safe)
    g_s16[(size_t)r * B_ + lane] = __float2half(0.0f);   // state_0 = 0
    if (r < GRID && lane == 0) g_flag[r << 5] = 0u;
    int gidx = r * 32 + lane;                             // zero 128000 counters
    if (gidx < T_ * GRID) g_ucnt[gidx] = 0;
    gidx += 65536;
    if (gidx < T_ * GRID) g_ucnt[gidx] = 0;
}

// ---------------- P2a: parallel-over-t classification + saturated states ------
__global__ void __launch_bounds__(NTHR)
phaseA_kernel(const float* __restrict__ x,        // [B,T,I]
              const float* __restrict__ win,      // [R,I]
              const float* __restrict__ noise,    // [B,R]
              float* __restrict__ states_out) {   // [B,T,R]
    __shared__ float ftile[RPC][B_ + 1];

    const int rb  = blockIdx.x;
    const int t0  = blockIdx.y * TCHUNK;
    const int tid = threadIdx.x;
    const int rl  = tid >> 5;                 // local row (warp)
    const int b   = tid & 31;                 // batch (lane)
    const int r   = rb * RPC + rl;

    // hoisted per-(r,b) constants
    const float w0 = win[r * 3 + 0];
    const float w1 = win[r * 3 + 1];
    const float w2 = win[r * 3 + 2];
    const float nzv = noise[(size_t)b * R_ + r];
    const float th  = g_thresh[r];
    const float* xb = x + (size_t)b * (T_ * I_);

    for (int t = t0; t < t0 + TCHUNK; t++) {
        float ax = fmaf(w0, xb[t * 3 + 0],
                   fmaf(w1, xb[t * 3 + 1],
                   fmaf(w2, xb[t * 3 + 2], nzv)));

        float val = 0.0f;                      // placeholder for unknowns
        if (fabsf(ax) > th) {
            val = (ax > 0.0f) ? 1.0f : -1.0f;  // exact: tanh saturates regardless of rec
        } else {
            int slot = atomicAdd(&g_ucnt[t * GRID + rb], 1);   // slot < 512 by construction
            g_unk[((size_t)(t * GRID + rb) << 9) + slot] =
                make_uint2((unsigned)((rl << 5) | b), __float_as_uint(ax));
        }

        // dense fp16 state for step t+1 (warp-coalesced 64B per row)
        g_s16[(size_t)(t + 1) * (R_ * B_) + (size_t)r * B_ + b] = __float2half_rn(val);
        if (t == T_ - 1) g_final[r * B_ + b] = val;            // phaseB fixes unknowns

        // transposed states_out write via SMEM (64B per half-warp)
        ftile[rl][b] = val;
        __syncthreads();
        {
            int b2 = rl + ((b >> 4) << 4);
            int rr = b & 15;
            states_out[(size_t)b2 * (T_ * R_) + (size_t)t * R_ + rb * RPC + rr] = ftile[rr][b2];
        }
        __syncthreads();                       // WAR on ftile before next t
    }
}

// ---------------- P2b: serial resolution of unsaturated entries ----------------
__global__ void __launch_bounds__(NTHR, 1)
phaseB_kernel(float* __restrict__ states_out) {  // [B,T,R]
    __shared__ uint2 snnz[RPC][CAP];             // (col*32, val bits) 20 KB
    __shared__ int   scnt[RPC];

    const int tid  = threadIdx.x;
    const int wid  = tid >> 5;                   // warp id (0..15)
    const int lane = tid & 31;
    const int cta  = blockIdx.x;

    // preload this block's 16 rows of nnz (reused all steps)
    {
        int r = cta * RPC + wid;
        int cnt = g_cnt[r];
        if (lane == 0) scnt[wid] = cnt;
        for (int k = lane; k < cnt; k += 32)
            snnz[wid][k] = make_uint2(g_cols[r][k], __float_as_uint(g_vals[r][k]));
    }
    // warm L2 for step 1: list + count for tau=1 (slab 0 freshly written by prep)
    {
        const int lb0 = 0 * GRID + cta;
        if (tid < 32) prefetch_l2((const char*)&g_unk[(size_t)lb0 << 9] + tid * 128);
        if (tid == 32) prefetch_l2(&g_ucnt[lb0]);
    }
    __syncthreads();

    for (int tau = 1; tau <= T_; tau++) {
        const __half* sp = g_s16 + (size_t)(tau - 1) * (R_ * B_);
        const int lbase = (tau - 1) * GRID + cta;
        const int ucnt = g_ucnt[lbase];

        for (int i = wid; i < ucnt; i += 16) {   // one warp per unknown pair
            uint2 e = g_unk[((size_t)lbase << 9) + i];
            int rl = (int)(e.x >> 5);
            int b  = (int)(e.x & 31);
            int pc = scnt[rl];

            float part = 0.0f;
            for (int k = lane; k < pc; k += 32) {
                uint2 cv = snnz[rl][k];
                part = fmaf(__uint_as_float(cv.y),
                            __half2float(sp[cv.x + b]), part);
            }
            #pragma unroll
            for (int d = 16; d; d >>= 1) part += __shfl_xor_sync(0xffffffffu, part, d);

            if (lane == 0) {
                float v = tanh_fast(__uint_as_float(e.y) + part);
                int rg = cta * RPC + rl;
                g_s16[(size_t)tau * (R_ * B_) + (size_t)rg * B_ + b] = __float2half_rn(v);
                states_out[(size_t)b * (T_ * R_) + (size_t)(tau - 1) * R_ + rg] = v;
                if (tau == T_) g_final[rg * B_ + b] = v;
            }
        }
        __syncthreads();                         // all corrections stored

        // arrival (release orders prior stores; bar.sync cumulative)
        if (tid == 0) st_rel(&g_flag[cta << 5], (unsigned)tau);

        // ---- off-critical-path L2 prefetch for step tau+1 ----
        if (tau < T_) {
            if (tid < 8) {
                // this CTA's 1KB share of slab tau; 128 CTAs cover all 128KB
                prefetch_l2((const char*)(g_s16 + (size_t)tau * (R_ * B_))
                            + cta * 1024 + tid * 128);
            } else if (tid < 40) {
                // full worst-case unknown list for (tau, cta): 512*8B = 32 lines
                prefetch_l2((const char*)&g_unk[(size_t)(tau * GRID + cta) << 9]
                            + (tid - 8) * 128);
            } else if (tid == 40) {
                prefetch_l2(&g_ucnt[tau * GRID + cta]);
            }
        }

        // flat barrier: 128 threads poll 128 distinct flag lines (acquire per read)
        if (tid < GRID) {
            while (ld_acq(&g_flag[tid << 5]) < (unsigned)tau) { }
        }
        __syncthreads();
    }
}

// ---------------- P3: output projection ----------------
__global__ void outproj_kernel(const float* __restrict__ wout,  // [O,R]
                               float* __restrict__ out) {       // [B*O]
    __shared__ float red[256];
    int pair = blockIdx.x;            // 0..95
    int b = pair / O_, o = pair - b * O_;

    float sum = 0.0f;
    for (int r = threadIdx.x; r < R_; r += blockDim.x)
        sum += g_final[r * B_ + b] * wout[o * R_ + r];

    red[threadIdx.x] = sum;
    __syncthreads();
    for (int s = 128; s > 0; s >>= 1) {
        if (threadIdx.x < s) red[threadIdx.x] += red[threadIdx.x + s];
        __syncthreads();
    }
    if (threadIdx.x == 0) out[b * O_ + o] = red[0];
}

// ---------------- launch ----------------
extern "C" void kernel_launch(void* const* d_in, const int* in_sizes, int n_in,
                              void* d_out, int out_size) {
    (void)in_sizes; (void)n_in; (void)out_size;
    const float* x     = (const float*)d_in[0];   // [B,T,I]
    const float* win   = (const float*)d_in[1];   // [R,I]
    const float* wres  = (const float*)d_in[2];   // [R,R]
    const float* wout  = (const float*)d_in[3];   // [O,R]
    const float* noise = (const float*)d_in[4];   // [B,R]
    float* out = (float*)d_out;                   // [B*O] then [B,T,R]

    prep_kernel<<<R_, 32>>>(wres);
    phaseA_kernel<<<dim3(GRID, T_ / TCHUNK), NTHR>>>(x, win, noise, out + B_ * O_);
    phaseB_kernel<<<GRID, NTHR>>>(out + B_ * O_);
    outproj_kernel<<<B_ * O_, 256>>>(wout, out);
}